// round 15
// baseline (speedup 1.0000x reference)
#include <cuda_runtime.h>
#include <cuda_bf16.h>
#include <cstdint>
#include <math.h>

#define BB  8
#define NP  8192
#define SP  2048
#define DD1 64
#define DD2 128
#define CC0 192   // IN_CH
#define CC1 256
#define CC2 128
#define RTOT (BB*NP)   // 65536

// ---------------- scratch (device globals; no allocation) ----------------
__device__ float g_p2t[(size_t)BB*SP*DD2];
__device__ float g_p1t[(size_t)BB*NP*DD1];
__device__ int   g_idx[(size_t)RTOT*3];
__device__ float g_wgt[(size_t)RTOT*3];
__device__ __align__(16) __nv_bfloat16 g_ah[(size_t)RTOT*CC0];  // layer-0 A hi
__device__ __align__(16) __nv_bfloat16 g_al[(size_t)RTOT*CC0];  // layer-0 A lo
__device__ float g_y0[(size_t)RTOT*CC1];
__device__ float g_y1[(size_t)RTOT*CC2];
__device__ __align__(16) __nv_bfloat16 g_wh0[CC1*CC0], g_wl0[CC1*CC0];  // W0^T split [256][192]
__device__ __align__(16) __nv_bfloat16 g_wh1[CC2*CC1], g_wl1[CC2*CC1];  // W1^T split [128][256]
__device__ float g_sum0[CC1], g_sq0[CC1];
__device__ float g_sum1[CC2], g_sq1[CC2];

// ======================= PTX helpers =======================
__device__ __forceinline__ uint32_t smem_to_u32(const void* p) {
    uint32_t a;
    asm("{ .reg .u64 t; cvta.to.shared.u64 t, %1; cvt.u32.u64 %0, t; }" : "=r"(a) : "l"(p));
    return a;
}
#define SWZ128(off) ((off) ^ (((off) >> 3) & 0x70))
#define CP_ASYNC16(sm, gp) \
    asm volatile("cp.async.cg.shared.global [%0], [%1], 16;" :: "r"(sm), "l"(gp) : "memory")
#define CP_COMMIT() asm volatile("cp.async.commit_group;" ::: "memory")
#define CP_WAIT(n)  asm volatile("cp.async.wait_group %0;" :: "n"(n) : "memory")

__device__ __forceinline__ void ldm_x4(uint32_t* r, uint32_t addr) {
    asm volatile("ldmatrix.sync.aligned.m8n8.x4.shared.b16 {%0,%1,%2,%3}, [%4];"
        : "=r"(r[0]), "=r"(r[1]), "=r"(r[2]), "=r"(r[3]) : "r"(addr));
}
__device__ __forceinline__ void mma16816(float* c, const uint32_t* a, const uint32_t* b) {
    asm volatile("mma.sync.aligned.m16n8k16.row.col.f32.bf16.bf16.f32 "
        "{%0,%1,%2,%3}, {%4,%5,%6,%7}, {%8,%9}, {%0,%1,%2,%3};"
        : "+f"(c[0]), "+f"(c[1]), "+f"(c[2]), "+f"(c[3])
        : "r"(a[0]), "r"(a[1]), "r"(a[2]), "r"(a[3]), "r"(b[0]), "r"(b[1]));
}
// ---- packed f32x2 (Blackwell; PTX-only path) ----
__device__ __forceinline__ uint64_t pack2(float lo, float hi) {
    uint64_t r;
    asm("mov.b64 %0, {%1, %2};" : "=l"(r) : "f"(lo), "f"(hi));
    return r;
}
__device__ __forceinline__ uint64_t fma2(uint64_t a, uint64_t b, uint64_t c) {
    uint64_t d;
    asm("fma.rn.f32x2 %0, %1, %2, %3;" : "=l"(d) : "l"(a), "l"(b), "l"(c));
    return d;
}
__device__ __forceinline__ void unpack2(float& lo, float& hi, uint64_t v) {
    asm("mov.b64 {%0, %1}, %2;" : "=f"(lo), "=f"(hi) : "l"(v));
}

// ======================= fused prep: zero + tr_p2 + tr_p1 + wprep0 + wprep1 =======================
__global__ __launch_bounds__(256) void k_prep(const float* __restrict__ p2,
                                              const float* __restrict__ p1,
                                              const float* __restrict__ cw0,
                                              const float* __restrict__ cw1) {
    __shared__ float tile[32][33];
    int bid = blockIdx.x, tid = threadIdx.x;
    int tx = tid & 31, ty = tid >> 5;

    if (bid < 2048) {
        int i = bid;
        int s0 = (i & 63) * 32, c0 = ((i >> 6) & 3) * 32, b = i >> 8;
#pragma unroll
        for (int j = 0; j < 4; j++) {
            int c = c0 + ty + j * 8;
            tile[ty + j * 8][tx] = p2[((size_t)b * DD2 + c) * SP + s0 + tx];
        }
        __syncthreads();
#pragma unroll
        for (int j = 0; j < 4; j++) {
            int s = s0 + ty + j * 8;
            g_p2t[((size_t)b * SP + s) * DD2 + c0 + tx] = tile[tx][ty + j * 8];
        }
    } else if (bid < 6144) {
        int i = bid - 2048;
        int n0 = (i & 255) * 32, c0 = ((i >> 8) & 1) * 32, b = i >> 9;
#pragma unroll
        for (int j = 0; j < 4; j++) {
            int c = c0 + ty + j * 8;
            tile[ty + j * 8][tx] = p1[((size_t)b * DD1 + c) * NP + n0 + tx];
        }
        __syncthreads();
#pragma unroll
        for (int j = 0; j < 4; j++) {
            int n = n0 + ty + j * 8;
            g_p1t[((size_t)b * NP + n) * DD1 + c0 + tx] = tile[tx][ty + j * 8];
        }
    } else if (bid < 6336) {
        int i = (bid - 6144) * 256 + tid;
        int n = i / CC0, k = i % CC0;
        float v = cw0[(size_t)k * CC1 + n];
        __nv_bfloat16 h = __float2bfloat16(v);
        g_wh0[i] = h;
        g_wl0[i] = __float2bfloat16(v - __bfloat162float(h));
    } else if (bid < 6464) {
        int i = (bid - 6336) * 256 + tid;
        int n = i >> 8, k = i & 255;
        float v = cw1[(size_t)k * CC2 + n];
        __nv_bfloat16 h = __float2bfloat16(v);
        g_wh1[i] = h;
        g_wl1[i] = __float2bfloat16(v - __bfloat162float(h));
    } else {
        for (int i = tid; i < CC1; i += 256) { g_sum0[i] = 0.f; g_sq0[i] = 0.f; }
        for (int i = tid; i < CC2; i += 256) { g_sum1[i] = 0.f; g_sq1[i] = 0.f; }
    }
}

// ---------------- 3-NN (R10 measured optimum) ----------------
__device__ __forceinline__ void knn_insert(float dc, int ic,
                                           float& d0, float& d1, float& d2,
                                           int& i0, int& i1, int& i2) {
    if (dc < d1) {
        d2 = d1; i2 = i1;
        if (dc < d0) { d1 = d0; i1 = i0; d0 = dc; i0 = ic; }
        else         { d1 = dc; i1 = ic; }
    } else           { d2 = dc; i2 = ic; }
}

__global__ __launch_bounds__(512) void k_knn(const float* __restrict__ xyz1,
                                             const float* __restrict__ xyz2) {
    __shared__ ulonglong4 s_pp[SP / 2];   // 32KB
    int b = blockIdx.y, tid = threadIdx.x;
    const float* x2b = xyz2 + (size_t)b * 3 * SP;
    for (int t = tid; t < SP / 2; t += 512) {
        float xa = x2b[2 * t],          xb = x2b[2 * t + 1];
        float ya = x2b[SP + 2 * t],     yb = x2b[SP + 2 * t + 1];
        float za = x2b[2 * SP + 2 * t], zb = x2b[2 * SP + 2 * t + 1];
        ulonglong4 v;
        v.x = pack2(-2.f * xa, -2.f * xb);
        v.y = pack2(-2.f * ya, -2.f * yb);
        v.z = pack2(-2.f * za, -2.f * zb);
        v.w = pack2(xa * xa + ya * ya + za * za, xb * xb + yb * yb + zb * zb);
        s_pp[t] = v;
    }
    __syncthreads();

    int q = tid & 3;
    int qp = blockIdx.x * 256 + (tid >> 2) * 2;
    const float* x1b = xyz1 + (size_t)b * 3 * NP;
    float2 xq = *reinterpret_cast<const float2*>(x1b + qp);
    float2 yq = *reinterpret_cast<const float2*>(x1b + NP + qp);
    float2 zq = *reinterpret_cast<const float2*>(x1b + 2 * NP + qp);
    uint64_t xA = pack2(xq.x, xq.x), yA = pack2(yq.x, yq.x), zA = pack2(zq.x, zq.x);
    uint64_t xB = pack2(xq.y, xq.y), yB = pack2(yq.y, yq.y), zB = pack2(zq.y, zq.y);
    float nsqA = xq.x * xq.x + yq.x * yq.x + zq.x * zq.x;
    float nsqB = xq.y * xq.y + yq.y * yq.y + zq.y * zq.y;

    float d0A = 1e30f, d1A = 1e30f, d2A = 1e30f;
    float d0B = 1e30f, d1B = 1e30f, d2B = 1e30f;
    int   i0A = 0, i1A = 0, i2A = 0;
    int   i0B = 0, i1B = 0, i2B = 0;
#pragma unroll 4
    for (int i = 0; i < SP / 8; i++) {
        int t = i * 4 + q;
        ulonglong4 pp = s_pp[t];
        uint64_t ddA = fma2(xA, pp.x, fma2(yA, pp.y, fma2(zA, pp.z, pp.w)));
        uint64_t ddB = fma2(xB, pp.x, fma2(yB, pp.y, fma2(zB, pp.z, pp.w)));
        float a0, a1, b0, b1;
        unpack2(a0, a1, ddA);
        unpack2(b0, b1, ddB);
        if (a0 < d2A) knn_insert(a0, 2 * t,     d0A, d1A, d2A, i0A, i1A, i2A);
        if (a1 < d2A) knn_insert(a1, 2 * t + 1, d0A, d1A, d2A, i0A, i1A, i2A);
        if (b0 < d2B) knn_insert(b0, 2 * t,     d0B, d1B, d2B, i0B, i1B, i2B);
        if (b1 < d2B) knn_insert(b1, 2 * t + 1, d0B, d1B, d2B, i0B, i1B, i2B);
    }

#pragma unroll
    for (int x = 1; x < 4; x <<= 1) {
        float e0 = __shfl_xor_sync(0xffffffffu, d0A, x);
        float e1 = __shfl_xor_sync(0xffffffffu, d1A, x);
        float e2 = __shfl_xor_sync(0xffffffffu, d2A, x);
        int   j0 = __shfl_xor_sync(0xffffffffu, i0A, x);
        int   j1 = __shfl_xor_sync(0xffffffffu, i1A, x);
        int   j2 = __shfl_xor_sync(0xffffffffu, i2A, x);
        if (e0 < d2A) knn_insert(e0, j0, d0A, d1A, d2A, i0A, i1A, i2A);
        if (e1 < d2A) knn_insert(e1, j1, d0A, d1A, d2A, i0A, i1A, i2A);
        if (e2 < d2A) knn_insert(e2, j2, d0A, d1A, d2A, i0A, i1A, i2A);
        float f0 = __shfl_xor_sync(0xffffffffu, d0B, x);
        float f1 = __shfl_xor_sync(0xffffffffu, d1B, x);
        float f2 = __shfl_xor_sync(0xffffffffu, d2B, x);
        int   k0 = __shfl_xor_sync(0xffffffffu, i0B, x);
        int   k1 = __shfl_xor_sync(0xffffffffu, i1B, x);
        int   k2 = __shfl_xor_sync(0xffffffffu, i2B, x);
        if (f0 < d2B) knn_insert(f0, k0, d0B, d1B, d2B, i0B, i1B, i2B);
        if (f1 < d2B) knn_insert(f1, k1, d0B, d1B, d2B, i0B, i1B, i2B);
        if (f2 < d2B) knn_insert(f2, k2, d0B, d1B, d2B, i0B, i1B, i2B);
    }

    if (q == 0) {
        {
            float r0 = 1.f / (d0A + nsqA + 1e-8f);
            float r1 = 1.f / (d1A + nsqA + 1e-8f);
            float r2 = 1.f / (d2A + nsqA + 1e-8f);
            float inv = 1.f / (r0 + r1 + r2);
            size_t row = (size_t)b * NP + qp;
            g_idx[row * 3 + 0] = i0A;  g_wgt[row * 3 + 0] = r0 * inv;
            g_idx[row * 3 + 1] = i1A;  g_wgt[row * 3 + 1] = r1 * inv;
            g_idx[row * 3 + 2] = i2A;  g_wgt[row * 3 + 2] = r2 * inv;
        }
        {
            float r0 = 1.f / (d0B + nsqB + 1e-8f);
            float r1 = 1.f / (d1B + nsqB + 1e-8f);
            float r2 = 1.f / (d2B + nsqB + 1e-8f);
            float inv = 1.f / (r0 + r1 + r2);
            size_t row = (size_t)b * NP + qp + 1;
            g_idx[row * 3 + 0] = i0B;  g_wgt[row * 3 + 0] = r0 * inv;
            g_idx[row * 3 + 1] = i1B;  g_wgt[row * 3 + 1] = r1 * inv;
            g_idx[row * 3 + 2] = i2B;  g_wgt[row * 3 + 2] = r2 * inv;
        }
    }
}

// gather + interp + concat -> bf16 hi/lo A for layer 0 [R, 192]
__global__ __launch_bounds__(192) void k_gather() {
    size_t row = blockIdx.x;
    int b = (int)(row >> 13);
    int c = threadIdx.x;
    int   i0 = g_idx[row * 3 + 0], i1 = g_idx[row * 3 + 1], i2 = g_idx[row * 3 + 2];
    float w0 = g_wgt[row * 3 + 0], w1 = g_wgt[row * 3 + 1], w2 = g_wgt[row * 3 + 2];
    float v;
    if (c < DD1) {
        v = g_p1t[row * DD1 + c];
    } else {
        int cc = c - DD1;
        size_t base = (size_t)b * SP * DD2;
        v = w0 * g_p2t[base + (size_t)i0 * DD2 + cc]
          + w1 * g_p2t[base + (size_t)i1 * DD2 + cc]
          + w2 * g_p2t[base + (size_t)i2 * DD2 + cc];
    }
    __nv_bfloat16 h = __float2bfloat16(v);
    g_ah[row * CC0 + c] = h;
    g_al[row * CC0 + c] = __float2bfloat16(v - __bfloat162float(h));
}

// ======================= layer-0 mma GEMM: TRIPLE-buffered, 1 sync/chunk (+fused BN stats) =======================
template <int K, int N>
__global__ __launch_bounds__(256) void k_mma(const __nv_bfloat16* __restrict__ Ah,
                                             const __nv_bfloat16* __restrict__ Al,
                                             const __nv_bfloat16* __restrict__ Bh,
                                             const __nv_bfloat16* __restrict__ Bl,
                                             const float* __restrict__ bias,
                                             float* __restrict__ Cout,
                                             float* __restrict__ sumArr,
                                             float* __restrict__ sqArr) {
    constexpr int KC  = 64;
    constexpr int CPS = K / KC;
    constexpr int NC  = 3 * CPS;
    constexpr uint32_t TB = 16384;

    extern __shared__ __align__(1024) char smem[];
    uint32_t sbase = smem_to_u32(smem);
    // 3 stages: [A0 A1 A2 B0 B1 B2]
    const uint32_t offA[3] = {0u, TB, 2u * TB};
    const uint32_t offB[3] = {3u * TB, 4u * TB, 5u * TB};

    int tid  = threadIdx.x;
    int wid  = tid >> 5, lane = tid & 31;
    int wm   = wid & 1;
    int wn   = wid >> 1;
    int blockRow = blockIdx.y * 128;
    int blockCol = blockIdx.x * 128;

    float acc[4][4][4];
#pragma unroll
    for (int i = 0; i < 4; i++)
#pragma unroll
        for (int j = 0; j < 4; j++)
#pragma unroll
            for (int l = 0; l < 4; l++) acc[i][j][l] = 0.f;

    int lr = tid >> 3;
    int lq = tid & 7;

    auto load_chunk = [&](int c, int buf) {
        int seg = c / CPS;
        int kb  = (c % CPS) * KC;
        const __nv_bfloat16* Asrc = (seg == 1) ? Al : Ah;
        const __nv_bfloat16* Bsrc = (seg == 2) ? Bl : Bh;
#pragma unroll
        for (int it = 0; it < 4; it++) {
            int r = it * 32 + lr;
            const void* gp = Asrc + (size_t)(blockRow + r) * K + kb + lq * 8;
            CP_ASYNC16(sbase + offA[buf] + SWZ128((uint32_t)(r * 128 + lq * 16)), gp);
        }
#pragma unroll
        for (int it = 0; it < 4; it++) {
            int n = it * 32 + lr;
            const void* gp = Bsrc + (size_t)(blockCol + n) * K + kb + lq * 8;
            CP_ASYNC16(sbase + offB[buf] + SWZ128((uint32_t)(n * 128 + lq * 16)), gp);
        }
    };

    int aRowL = (lane & 15);
    int aKoff = (lane >> 4) * 16;
    int bRowL = (lane & 7) + ((lane >> 4) << 3);
    int bKoff = ((lane >> 3) & 1) * 16;

    load_chunk(0, 0);
    CP_COMMIT();
    load_chunk(1, 1);
    CP_COMMIT();

    for (int c = 0; c < NC; c++) {
        int buf = c % 3;
        // chunk c must be resident: with ≤2 groups in flight, wait_group(1) completes group c.
        if (c == NC - 1) { CP_WAIT(0); } else { CP_WAIT(1); }
        __syncthreads();   // also guarantees all warps finished mma(c-1) -> stage (c+2)%3 reusable
        if (c + 2 < NC) {
            load_chunk(c + 2, (c + 2) % 3);
            CP_COMMIT();
        }

        uint32_t aBase = sbase + offA[buf];
        uint32_t bBase = sbase + offB[buf];
#pragma unroll
        for (int kk = 0; kk < 4; kk++) {
            uint32_t afr[4][4];
#pragma unroll
            for (int mt = 0; mt < 4; mt++) {
                int row = wm * 64 + mt * 16 + aRowL;
                ldm_x4(afr[mt], aBase + SWZ128((uint32_t)(row * 128 + kk * 32 + aKoff)));
            }
            uint32_t bfr[2][4];
#pragma unroll
            for (int nt = 0; nt < 2; nt++) {
                int row = wn * 32 + nt * 16 + bRowL;
                ldm_x4(bfr[nt], bBase + SWZ128((uint32_t)(row * 128 + kk * 32 + bKoff)));
            }
#pragma unroll
            for (int mt = 0; mt < 4; mt++)
#pragma unroll
                for (int n8 = 0; n8 < 4; n8++)
                    mma16816(acc[mt][n8], afr[mt], &bfr[n8 >> 1][(n8 & 1) * 2]);
        }
    }

    int g = lane >> 2, tig = lane & 3;
    float sA[4][2], qA[4][2];
#pragma unroll
    for (int n8 = 0; n8 < 4; n8++) { sA[n8][0] = sA[n8][1] = qA[n8][0] = qA[n8][1] = 0.f; }

#pragma unroll
    for (int mt = 0; mt < 4; mt++) {
        int row0 = blockRow + wm * 64 + mt * 16 + g;
#pragma unroll
        for (int n8 = 0; n8 < 4; n8++) {
            int col = blockCol + wn * 32 + n8 * 8 + tig * 2;
            float b0 = __ldg(bias + col), b1 = __ldg(bias + col + 1);
            float2 v0 = make_float2(acc[mt][n8][0] + b0, acc[mt][n8][1] + b1);
            float2 v1 = make_float2(acc[mt][n8][2] + b0, acc[mt][n8][3] + b1);
            *reinterpret_cast<float2*>(Cout + (size_t)row0 * N + col) = v0;
            *reinterpret_cast<float2*>(Cout + (size_t)(row0 + 8) * N + col) = v1;
            sA[n8][0] += v0.x + v1.x;
            sA[n8][1] += v0.y + v1.y;
            qA[n8][0] = fmaf(v0.x, v0.x, fmaf(v1.x, v1.x, qA[n8][0]));
            qA[n8][1] = fmaf(v0.y, v0.y, fmaf(v1.y, v1.y, qA[n8][1]));
        }
    }
#pragma unroll
    for (int x = 4; x < 32; x <<= 1) {
#pragma unroll
        for (int n8 = 0; n8 < 4; n8++) {
            sA[n8][0] += __shfl_xor_sync(0xffffffffu, sA[n8][0], x);
            sA[n8][1] += __shfl_xor_sync(0xffffffffu, sA[n8][1], x);
            qA[n8][0] += __shfl_xor_sync(0xffffffffu, qA[n8][0], x);
            qA[n8][1] += __shfl_xor_sync(0xffffffffu, qA[n8][1], x);
        }
    }
    if (lane < 4) {
#pragma unroll
        for (int n8 = 0; n8 < 4; n8++) {
            int col = blockCol + wn * 32 + n8 * 8 + tig * 2;
            atomicAdd(sumArr + col,     sA[n8][0]);
            atomicAdd(sumArr + col + 1, sA[n8][1]);
            atomicAdd(sqArr + col,      qA[n8][0]);
            atomicAdd(sqArr + col + 1,  qA[n8][1]);
        }
    }
}

// ======================= layer-1 GEMM, fused BN0-finalize + BN0+relu+split A-producer =======================
__global__ __launch_bounds__(256) void k_mma1(const float* __restrict__ Y0,
                                              const __nv_bfloat16* __restrict__ Bh,
                                              const __nv_bfloat16* __restrict__ Bl,
                                              const float* __restrict__ sum0,
                                              const float* __restrict__ sq0,
                                              const float* __restrict__ scale0,
                                              const float* __restrict__ bnb0,
                                              const float* __restrict__ bias,
                                              float* __restrict__ Cout,
                                              float* __restrict__ sumArr,
                                              float* __restrict__ sqArr) {
    constexpr int K = 256, N = 128, CPS = 4;
    extern __shared__ __align__(1024) char smem[];
    uint32_t sbase = smem_to_u32(smem);
    const uint32_t offAh[2] = {0u, 32768u};
    const uint32_t offAl[2] = {16384u, 49152u};
    const uint32_t offBh = 65536u, offBl = 131072u;
    float* s_bnA = reinterpret_cast<float*>(smem + 196608);   // [256]
    float* s_bnC = s_bnA + 256;                                // [256]

    int tid = threadIdx.x, wid = tid >> 5, lane = tid & 31;
    int wm = wid & 1, wn = wid >> 1;
    int blockRow = blockIdx.y * 128;

    for (int gidx = tid; gidx < 4096; gidx += 256) {
        int n = gidx >> 5, kq = gidx & 31;
        int c = kq >> 3, qq = kq & 7;
        uint32_t so = SWZ128((uint32_t)(n * 128 + qq * 16)) + (uint32_t)c * 16384u;
        CP_ASYNC16(sbase + offBh + so, Bh + (size_t)n * K + kq * 8);
        CP_ASYNC16(sbase + offBl + so, Bl + (size_t)n * K + kq * 8);
    }
    CP_COMMIT();

    {
        float mu  = sum0[tid] * (1.f / (float)RTOT);
        float var = sq0[tid] * (1.f / (float)RTOT) - mu * mu;
        float a   = rsqrtf(var + 1e-5f) * scale0[tid];
        s_bnA[tid] = a;
        s_bnC[tid] = bnb0[tid] - mu * a;
    }

    float acc[4][4][4];
#pragma unroll
    for (int i = 0; i < 4; i++)
#pragma unroll
        for (int j = 0; j < 4; j++)
#pragma unroll
            for (int l = 0; l < 4; l++) acc[i][j][l] = 0.f;

    float4 stg[8];
    auto ldgA = [&](int c) {
#pragma unroll
        for (int it = 0; it < 8; it++) {
            int gi = it * 256 + tid;
            int r = gi >> 4, kq4 = gi & 15;
            stg[it] = *reinterpret_cast<const float4*>(
                Y0 + (size_t)(blockRow + r) * K + c * 64 + kq4 * 4);
        }
    };
    auto stsA = [&](int c, int buf) {
#pragma unroll
        for (int it = 0; it < 8; it++) {
            int gi = it * 256 + tid;
            int r = gi >> 4, kq4 = gi & 15;
            int k = c * 64 + kq4 * 4;
            float4 a4 = *reinterpret_cast<const float4*>(s_bnA + k);
            float4 c4 = *reinterpret_cast<const float4*>(s_bnC + k);
            float v0 = fmaxf(fmaf(stg[it].x, a4.x, c4.x), 0.f);
            float v1 = fmaxf(fmaf(stg[it].y, a4.y, c4.y), 0.f);
            float v2 = fmaxf(fmaf(stg[it].z, a4.z, c4.z), 0.f);
            float v3 = fmaxf(fmaf(stg[it].w, a4.w, c4.w), 0.f);
            __nv_bfloat16 h0 = __float2bfloat16(v0), h1 = __float2bfloat16(v1);
            __nv_bfloat16 h2 = __float2bfloat16(v2), h3 = __float2bfloat16(v3);
            __nv_bfloat162 hp0; hp0.x = h0; hp0.y = h1;
            __nv_bfloat162 hp1; hp1.x = h2; hp1.y = h3;
            __nv_bfloat162 lp0, lp1;
            lp0.x = __float2bfloat16(v0 - __bfloat162float(h0));
            lp0.y = __float2bfloat16(v1 - __bfloat162float(h1));
            lp1.x = __float2bfloat16(v2 - __bfloat162float(h2));
            lp1.y = __float2bfloat16(v3 - __bfloat162float(h3));
            uint32_t sw = SWZ128((uint32_t)(r * 128 + (kq4 >> 1) * 16)) + (uint32_t)(kq4 & 1) * 8u;
            uint2 hv = make_uint2(*reinterpret_cast<uint32_t*>(&hp0),
                                  *reinterpret_cast<uint32_t*>(&hp1));
            uint2 lv = make_uint2(*reinterpret_cast<uint32_t*>(&lp0),
                                  *reinterpret_cast<uint32_t*>(&lp1));
            *reinterpret_cast<uint2*>(smem + offAh[buf] + sw) = hv;
            *reinterpret_cast<uint2*>(smem + offAl[buf] + sw) = lv;
        }
    };

    int aRowL = (lane & 15);
    int aKoff = (lane >> 4) * 16;
    int bRowL = (lane & 7) + ((lane >> 4) << 3);
    int bKoff = ((lane >> 3) & 1) * 16;

    ldgA(0);
    __syncthreads();
    stsA(0, 0);
    CP_WAIT(0);
    __syncthreads();

    for (int c = 0; c < CPS; c++) {
        int buf = c & 1;
        if (c + 1 < CPS) ldgA(c + 1);

        uint32_t bCh = sbase + offBh + (uint32_t)c * 16384u;
        uint32_t bCl = sbase + offBl + (uint32_t)c * 16384u;
#pragma unroll
        for (int pass = 0; pass < 3; pass++) {
            uint32_t aBase = sbase + ((pass == 1) ? offAl[buf] : offAh[buf]);
            uint32_t bBase = (pass == 2) ? bCl : bCh;
#pragma unroll
            for (int kk = 0; kk < 4; kk++) {
                uint32_t afr[4][4];
#pragma unroll
                for (int mt = 0; mt < 4; mt++) {
                    int row = wm * 64 + mt * 16 + aRowL;
                    ldm_x4(afr[mt], aBase + SWZ128((uint32_t)(row * 128 + kk * 32 + aKoff)));
                }
                uint32_t bfr[2][4];
#pragma unroll
                for (int nt = 0; nt < 2; nt++) {
                    int row = wn * 32 + nt * 16 + bRowL;
                    ldm_x4(bfr[nt], bBase + SWZ128((uint32_t)(row * 128 + kk * 32 + bKoff)));
                }
#pragma unroll
                for (int mt = 0; mt < 4; mt++)
#pragma unroll
                    for (int n8 = 0; n8 < 4; n8++)
                        mma16816(acc[mt][n8], afr[mt], &bfr[n8 >> 1][(n8 & 1) * 2]);
            }
        }
        if (c + 1 < CPS) stsA(c + 1, buf ^ 1);
        __syncthreads();
    }

    int g = lane >> 2, tig = lane & 3;
    float sA[4][2], qA[4][2];
#pragma unroll
    for (int n8 = 0; n8 < 4; n8++) { sA[n8][0] = sA[n8][1] = qA[n8][0] = qA[n8][1] = 0.f; }

#pragma unroll
    for (int mt = 0; mt < 4; mt++) {
        int row0 = blockRow + wm * 64 + mt * 16 + g;
#pragma unroll
        for (int n8 = 0; n8 < 4; n8++) {
            int col = wn * 32 + n8 * 8 + tig * 2;
            float b0 = __ldg(bias + col), b1 = __ldg(bias + col + 1);
            float2 v0 = make_float2(acc[mt][n8][0] + b0, acc[mt][n8][1] + b1);
            float2 v1 = make_float2(acc[mt][n8][2] + b0, acc[mt][n8][3] + b1);
            *reinterpret_cast<float2*>(Cout + (size_t)row0 * N + col) = v0;
            *reinterpret_cast<float2*>(Cout + (size_t)(row0 + 8) * N + col) = v1;
            sA[n8][0] += v0.x + v1.x;
            sA[n8][1] += v0.y + v1.y;
            qA[n8][0] = fmaf(v0.x, v0.x, fmaf(v1.x, v1.x, qA[n8][0]));
            qA[n8][1] = fmaf(v0.y, v0.y, fmaf(v1.y, v1.y, qA[n8][1]));
        }
    }
#pragma unroll
    for (int x = 4; x < 32; x <<= 1) {
#pragma unroll
        for (int n8 = 0; n8 < 4; n8++) {
            sA[n8][0] += __shfl_xor_sync(0xffffffffu, sA[n8][0], x);
            sA[n8][1] += __shfl_xor_sync(0xffffffffu, sA[n8][1], x);
            qA[n8][0] += __shfl_xor_sync(0xffffffffu, qA[n8][0], x);
            qA[n8][1] += __shfl_xor_sync(0xffffffffu, qA[n8][1], x);
        }
    }
    if (lane < 4) {
#pragma unroll
        for (int n8 = 0; n8 < 4; n8++) {
            int col = wn * 32 + n8 * 8 + tig * 2;
            atomicAdd(sumArr + col,     sA[n8][0]);
            atomicAdd(sumArr + col + 1, sA[n8][1]);
            atomicAdd(sqArr + col,      qA[n8][0]);
            atomicAdd(sqArr + col + 1,  qA[n8][1]);
        }
    }
}

// BN1-finalize (per block) + BN1 + relu + transpose to [B, C2, N]
__global__ __launch_bounds__(256) void k_out(const float* __restrict__ sum1,
                                             const float* __restrict__ sq1,
                                             const float* __restrict__ scale1,
                                             const float* __restrict__ bnb1,
                                             float* __restrict__ out) {
    __shared__ float tile[32][33];
    __shared__ float s_a1[32], s_c1[32];
    int b = blockIdx.z, n0 = blockIdx.x * 32, c0 = blockIdx.y * 32;
    int tx = threadIdx.x, ty = threadIdx.y;
    int flat = ty * 32 + tx;
    if (flat < 32) {
        int c = c0 + flat;
        float mu  = sum1[c] * (1.f / (float)RTOT);
        float var = sq1[c] * (1.f / (float)RTOT) - mu * mu;
        float a   = rsqrtf(var + 1e-5f) * scale1[c];
        s_a1[flat] = a;
        s_c1[flat] = bnb1[c] - mu * a;
    }
    __syncthreads();
#pragma unroll
    for (int j = 0; j < 4; j++) {
        int n = n0 + ty + j * 8;
        float v = g_y1[((size_t)b * NP + n) * CC2 + c0 + tx];
        v = fmaxf(fmaf(v, s_a1[tx], s_c1[tx]), 0.f);
        tile[ty + j * 8][tx] = v;
    }
    __syncthreads();
#pragma unroll
    for (int j = 0; j < 4; j++) {
        int c = c0 + ty + j * 8;
        out[((size_t)b * CC2 + c) * NP + n0 + tx] = tile[tx][ty + j * 8];
    }
}

// ======================= launch =======================
extern "C" void kernel_launch(void* const* d_in, const int* in_sizes, int n_in,
                              void* d_out, int out_size) {
    const float* xyz1 = (const float*)d_in[0];
    const float* xyz2 = (const float*)d_in[1];
    const float* pts1 = (const float*)d_in[2];
    const float* pts2 = (const float*)d_in[3];
    const float* cw0  = (const float*)d_in[4];
    const float* cb0  = (const float*)d_in[5];
    const float* bns0 = (const float*)d_in[6];
    const float* bnb0 = (const float*)d_in[7];
    const float* cw1  = (const float*)d_in[8];
    const float* cb1  = (const float*)d_in[9];
    const float* bns1 = (const float*)d_in[10];
    const float* bnb1 = (const float*)d_in[11];
    float* out = (float*)d_out;

    float *p_y0, *p_y1, *p_sum0, *p_sq0, *p_sum1, *p_sq1;
    __nv_bfloat16 *p_ah, *p_al, *p_wh0, *p_wl0, *p_wh1, *p_wl1;
    cudaGetSymbolAddress((void**)&p_y0, g_y0);
    cudaGetSymbolAddress((void**)&p_y1, g_y1);
    cudaGetSymbolAddress((void**)&p_sum0, g_sum0);
    cudaGetSymbolAddress((void**)&p_sq0, g_sq0);
    cudaGetSymbolAddress((void**)&p_sum1, g_sum1);
    cudaGetSymbolAddress((void**)&p_sq1, g_sq1);
    cudaGetSymbolAddress((void**)&p_ah, g_ah);
    cudaGetSymbolAddress((void**)&p_al, g_al);
    cudaGetSymbolAddress((void**)&p_wh0, g_wh0);
    cudaGetSymbolAddress((void**)&p_wl0, g_wl0);
    cudaGetSymbolAddress((void**)&p_wh1, g_wh1);
    cudaGetSymbolAddress((void**)&p_wl1, g_wl1);

    constexpr int SMEM_MMA  = 6 * 16384;          // 96KB  (layer 0, 3 stages)
    constexpr int SMEM_MMA1 = 192 * 1024 + 2048;  // 194KB (layer 1 + bn coeffs)
    cudaFuncSetAttribute((void*)k_mma<CC0, CC1>, cudaFuncAttributeMaxDynamicSharedMemorySize, SMEM_MMA);
    cudaFuncSetAttribute((void*)k_mma1, cudaFuncAttributeMaxDynamicSharedMemorySize, SMEM_MMA1);

    k_prep<<<6465, 256>>>(pts2, pts1, cw0, cw1);
    k_knn<<<dim3(NP / 256, BB), 512>>>(xyz1, xyz2);
    k_gather<<<RTOT, 192>>>();

    // layer 0: [R,192] x [256,192]^T -> y0 [R,256]  (+ fused stats)
    k_mma<CC0, CC1><<<dim3(CC1 / 128, RTOT / 128), 256, SMEM_MMA>>>(
        p_ah, p_al, p_wh0, p_wl0, cb0, p_y0, p_sum0, p_sq0);

    // layer 1: fused BN0-finalize + BN0+relu+split producer (+ fused stats)
    k_mma1<<<dim3(1, RTOT / 128), 256, SMEM_MMA1>>>(
        p_y0, p_wh1, p_wl1, p_sum0, p_sq0, bns0, bnb0, cb1, p_y1, p_sum1, p_sq1);

    // output: fused BN1-finalize + BN1 + relu + transpose
    k_out<<<dim3(NP / 32, CC2 / 32, BB), dim3(32, 8)>>>(p_sum1, p_sq1, bns1, bnb1, out);
}

// round 17
// speedup vs baseline: 1.0117x; 1.0117x over previous
#include <cuda_runtime.h>
#include <cuda_bf16.h>
#include <cstdint>
#include <math.h>

#define BB  8
#define NP  8192
#define SP  2048
#define DD1 64
#define DD2 128
#define CC0 192   // IN_CH
#define CC1 256
#define CC2 128
#define RTOT (BB*NP)   // 65536

// ---------------- scratch (device globals; no allocation) ----------------
__device__ float g_p2t[(size_t)BB*SP*DD2];
__device__ float g_p1t[(size_t)BB*NP*DD1];
__device__ int   g_idx[(size_t)RTOT*3];
__device__ float g_wgt[(size_t)RTOT*3];
__device__ __align__(16) __nv_bfloat16 g_ah[(size_t)RTOT*CC0];  // layer-0 A hi
__device__ __align__(16) __nv_bfloat16 g_al[(size_t)RTOT*CC0];  // layer-0 A lo
__device__ float g_y0[(size_t)RTOT*CC1];
__device__ float g_y1[(size_t)RTOT*CC2];
__device__ __align__(16) __nv_bfloat16 g_wh0[CC1*CC0], g_wl0[CC1*CC0];  // W0^T split [256][192]
__device__ __align__(16) __nv_bfloat16 g_wh1[CC2*CC1], g_wl1[CC2*CC1];  // W1^T split [128][256]
__device__ float g_sum0[CC1], g_sq0[CC1];
__device__ float g_sum1[CC2], g_sq1[CC2];

// ======================= PTX helpers =======================
__device__ __forceinline__ uint32_t smem_to_u32(const void* p) {
    uint32_t a;
    asm("{ .reg .u64 t; cvta.to.shared.u64 t, %1; cvt.u32.u64 %0, t; }" : "=r"(a) : "l"(p));
    return a;
}
#define SWZ128(off) ((off) ^ (((off) >> 3) & 0x70))
#define CP_ASYNC16(sm, gp) \
    asm volatile("cp.async.cg.shared.global [%0], [%1], 16;" :: "r"(sm), "l"(gp) : "memory")
#define CP_COMMIT() asm volatile("cp.async.commit_group;" ::: "memory")
#define CP_WAIT(n)  asm volatile("cp.async.wait_group %0;" :: "n"(n) : "memory")

__device__ __forceinline__ void ldm_x4(uint32_t* r, uint32_t addr) {
    asm volatile("ldmatrix.sync.aligned.m8n8.x4.shared.b16 {%0,%1,%2,%3}, [%4];"
        : "=r"(r[0]), "=r"(r[1]), "=r"(r[2]), "=r"(r[3]) : "r"(addr));
}
__device__ __forceinline__ void mma16816(float* c, const uint32_t* a, const uint32_t* b) {
    asm volatile("mma.sync.aligned.m16n8k16.row.col.f32.bf16.bf16.f32 "
        "{%0,%1,%2,%3}, {%4,%5,%6,%7}, {%8,%9}, {%0,%1,%2,%3};"
        : "+f"(c[0]), "+f"(c[1]), "+f"(c[2]), "+f"(c[3])
        : "r"(a[0]), "r"(a[1]), "r"(a[2]), "r"(a[3]), "r"(b[0]), "r"(b[1]));
}
// ---- packed f32x2 (Blackwell; PTX-only path) ----
__device__ __forceinline__ uint64_t pack2(float lo, float hi) {
    uint64_t r;
    asm("mov.b64 %0, {%1, %2};" : "=l"(r) : "f"(lo), "f"(hi));
    return r;
}
__device__ __forceinline__ uint64_t fma2(uint64_t a, uint64_t b, uint64_t c) {
    uint64_t d;
    asm("fma.rn.f32x2 %0, %1, %2, %3;" : "=l"(d) : "l"(a), "l"(b), "l"(c));
    return d;
}
__device__ __forceinline__ void unpack2(float& lo, float& hi, uint64_t v) {
    asm("mov.b64 {%0, %1}, %2;" : "=f"(lo), "=f"(hi) : "l"(v));
}

// ======================= fused prep: zero + tr_p2 + tr_p1 + wprep0 + wprep1 =======================
__global__ __launch_bounds__(256) void k_prep(const float* __restrict__ p2,
                                              const float* __restrict__ p1,
                                              const float* __restrict__ cw0,
                                              const float* __restrict__ cw1) {
    __shared__ float tile[32][33];
    int bid = blockIdx.x, tid = threadIdx.x;
    int tx = tid & 31, ty = tid >> 5;

    if (bid < 2048) {
        int i = bid;
        int s0 = (i & 63) * 32, c0 = ((i >> 6) & 3) * 32, b = i >> 8;
#pragma unroll
        for (int j = 0; j < 4; j++) {
            int c = c0 + ty + j * 8;
            tile[ty + j * 8][tx] = p2[((size_t)b * DD2 + c) * SP + s0 + tx];
        }
        __syncthreads();
#pragma unroll
        for (int j = 0; j < 4; j++) {
            int s = s0 + ty + j * 8;
            g_p2t[((size_t)b * SP + s) * DD2 + c0 + tx] = tile[tx][ty + j * 8];
        }
    } else if (bid < 6144) {
        int i = bid - 2048;
        int n0 = (i & 255) * 32, c0 = ((i >> 8) & 1) * 32, b = i >> 9;
#pragma unroll
        for (int j = 0; j < 4; j++) {
            int c = c0 + ty + j * 8;
            tile[ty + j * 8][tx] = p1[((size_t)b * DD1 + c) * NP + n0 + tx];
        }
        __syncthreads();
#pragma unroll
        for (int j = 0; j < 4; j++) {
            int n = n0 + ty + j * 8;
            g_p1t[((size_t)b * NP + n) * DD1 + c0 + tx] = tile[tx][ty + j * 8];
        }
    } else if (bid < 6336) {
        int i = (bid - 6144) * 256 + tid;
        int n = i / CC0, k = i % CC0;
        float v = cw0[(size_t)k * CC1 + n];
        __nv_bfloat16 h = __float2bfloat16(v);
        g_wh0[i] = h;
        g_wl0[i] = __float2bfloat16(v - __bfloat162float(h));
    } else if (bid < 6464) {
        int i = (bid - 6336) * 256 + tid;
        int n = i >> 8, k = i & 255;
        float v = cw1[(size_t)k * CC2 + n];
        __nv_bfloat16 h = __float2bfloat16(v);
        g_wh1[i] = h;
        g_wl1[i] = __float2bfloat16(v - __bfloat162float(h));
    } else {
        for (int i = tid; i < CC1; i += 256) { g_sum0[i] = 0.f; g_sq0[i] = 0.f; }
        for (int i = tid; i < CC2; i += 256) { g_sum1[i] = 0.f; g_sq1[i] = 0.f; }
    }
}

// ---------------- 3-NN (R10 measured optimum) ----------------
__device__ __forceinline__ void knn_insert(float dc, int ic,
                                           float& d0, float& d1, float& d2,
                                           int& i0, int& i1, int& i2) {
    if (dc < d1) {
        d2 = d1; i2 = i1;
        if (dc < d0) { d1 = d0; i1 = i0; d0 = dc; i0 = ic; }
        else         { d1 = dc; i1 = ic; }
    } else           { d2 = dc; i2 = ic; }
}

__global__ __launch_bounds__(512) void k_knn(const float* __restrict__ xyz1,
                                             const float* __restrict__ xyz2) {
    __shared__ ulonglong4 s_pp[SP / 2];   // 32KB
    int b = blockIdx.y, tid = threadIdx.x;
    const float* x2b = xyz2 + (size_t)b * 3 * SP;
    for (int t = tid; t < SP / 2; t += 512) {
        float xa = x2b[2 * t],          xb = x2b[2 * t + 1];
        float ya = x2b[SP + 2 * t],     yb = x2b[SP + 2 * t + 1];
        float za = x2b[2 * SP + 2 * t], zb = x2b[2 * SP + 2 * t + 1];
        ulonglong4 v;
        v.x = pack2(-2.f * xa, -2.f * xb);
        v.y = pack2(-2.f * ya, -2.f * yb);
        v.z = pack2(-2.f * za, -2.f * zb);
        v.w = pack2(xa * xa + ya * ya + za * za, xb * xb + yb * yb + zb * zb);
        s_pp[t] = v;
    }
    __syncthreads();

    int q = tid & 3;
    int qp = blockIdx.x * 256 + (tid >> 2) * 2;
    const float* x1b = xyz1 + (size_t)b * 3 * NP;
    float2 xq = *reinterpret_cast<const float2*>(x1b + qp);
    float2 yq = *reinterpret_cast<const float2*>(x1b + NP + qp);
    float2 zq = *reinterpret_cast<const float2*>(x1b + 2 * NP + qp);
    uint64_t xA = pack2(xq.x, xq.x), yA = pack2(yq.x, yq.x), zA = pack2(zq.x, zq.x);
    uint64_t xB = pack2(xq.y, xq.y), yB = pack2(yq.y, yq.y), zB = pack2(zq.y, zq.y);
    float nsqA = xq.x * xq.x + yq.x * yq.x + zq.x * zq.x;
    float nsqB = xq.y * xq.y + yq.y * yq.y + zq.y * zq.y;

    float d0A = 1e30f, d1A = 1e30f, d2A = 1e30f;
    float d0B = 1e30f, d1B = 1e30f, d2B = 1e30f;
    int   i0A = 0, i1A = 0, i2A = 0;
    int   i0B = 0, i1B = 0, i2B = 0;
#pragma unroll 4
    for (int i = 0; i < SP / 8; i++) {
        int t = i * 4 + q;
        ulonglong4 pp = s_pp[t];
        uint64_t ddA = fma2(xA, pp.x, fma2(yA, pp.y, fma2(zA, pp.z, pp.w)));
        uint64_t ddB = fma2(xB, pp.x, fma2(yB, pp.y, fma2(zB, pp.z, pp.w)));
        float a0, a1, b0, b1;
        unpack2(a0, a1, ddA);
        unpack2(b0, b1, ddB);
        if (a0 < d2A) knn_insert(a0, 2 * t,     d0A, d1A, d2A, i0A, i1A, i2A);
        if (a1 < d2A) knn_insert(a1, 2 * t + 1, d0A, d1A, d2A, i0A, i1A, i2A);
        if (b0 < d2B) knn_insert(b0, 2 * t,     d0B, d1B, d2B, i0B, i1B, i2B);
        if (b1 < d2B) knn_insert(b1, 2 * t + 1, d0B, d1B, d2B, i0B, i1B, i2B);
    }

#pragma unroll
    for (int x = 1; x < 4; x <<= 1) {
        float e0 = __shfl_xor_sync(0xffffffffu, d0A, x);
        float e1 = __shfl_xor_sync(0xffffffffu, d1A, x);
        float e2 = __shfl_xor_sync(0xffffffffu, d2A, x);
        int   j0 = __shfl_xor_sync(0xffffffffu, i0A, x);
        int   j1 = __shfl_xor_sync(0xffffffffu, i1A, x);
        int   j2 = __shfl_xor_sync(0xffffffffu, i2A, x);
        if (e0 < d2A) knn_insert(e0, j0, d0A, d1A, d2A, i0A, i1A, i2A);
        if (e1 < d2A) knn_insert(e1, j1, d0A, d1A, d2A, i0A, i1A, i2A);
        if (e2 < d2A) knn_insert(e2, j2, d0A, d1A, d2A, i0A, i1A, i2A);
        float f0 = __shfl_xor_sync(0xffffffffu, d0B, x);
        float f1 = __shfl_xor_sync(0xffffffffu, d1B, x);
        float f2 = __shfl_xor_sync(0xffffffffu, d2B, x);
        int   k0 = __shfl_xor_sync(0xffffffffu, i0B, x);
        int   k1 = __shfl_xor_sync(0xffffffffu, i1B, x);
        int   k2 = __shfl_xor_sync(0xffffffffu, i2B, x);
        if (f0 < d2B) knn_insert(f0, k0, d0B, d1B, d2B, i0B, i1B, i2B);
        if (f1 < d2B) knn_insert(f1, k1, d0B, d1B, d2B, i0B, i1B, i2B);
        if (f2 < d2B) knn_insert(f2, k2, d0B, d1B, d2B, i0B, i1B, i2B);
    }

    if (q == 0) {
        {
            float r0 = 1.f / (d0A + nsqA + 1e-8f);
            float r1 = 1.f / (d1A + nsqA + 1e-8f);
            float r2 = 1.f / (d2A + nsqA + 1e-8f);
            float inv = 1.f / (r0 + r1 + r2);
            size_t row = (size_t)b * NP + qp;
            g_idx[row * 3 + 0] = i0A;  g_wgt[row * 3 + 0] = r0 * inv;
            g_idx[row * 3 + 1] = i1A;  g_wgt[row * 3 + 1] = r1 * inv;
            g_idx[row * 3 + 2] = i2A;  g_wgt[row * 3 + 2] = r2 * inv;
        }
        {
            float r0 = 1.f / (d0B + nsqB + 1e-8f);
            float r1 = 1.f / (d1B + nsqB + 1e-8f);
            float r2 = 1.f / (d2B + nsqB + 1e-8f);
            float inv = 1.f / (r0 + r1 + r2);
            size_t row = (size_t)b * NP + qp + 1;
            g_idx[row * 3 + 0] = i0B;  g_wgt[row * 3 + 0] = r0 * inv;
            g_idx[row * 3 + 1] = i1B;  g_wgt[row * 3 + 1] = r1 * inv;
            g_idx[row * 3 + 2] = i2B;  g_wgt[row * 3 + 2] = r2 * inv;
        }
    }
}

// gather + interp + concat -> bf16 hi/lo A for layer 0 [R, 192]
__global__ __launch_bounds__(192) void k_gather() {
    size_t row = blockIdx.x;
    int b = (int)(row >> 13);
    int c = threadIdx.x;
    int   i0 = g_idx[row * 3 + 0], i1 = g_idx[row * 3 + 1], i2 = g_idx[row * 3 + 2];
    float w0 = g_wgt[row * 3 + 0], w1 = g_wgt[row * 3 + 1], w2 = g_wgt[row * 3 + 2];
    float v;
    if (c < DD1) {
        v = g_p1t[row * DD1 + c];
    } else {
        int cc = c - DD1;
        size_t base = (size_t)b * SP * DD2;
        v = w0 * g_p2t[base + (size_t)i0 * DD2 + cc]
          + w1 * g_p2t[base + (size_t)i1 * DD2 + cc]
          + w2 * g_p2t[base + (size_t)i2 * DD2 + cc];
    }
    __nv_bfloat16 h = __float2bfloat16(v);
    g_ah[row * CC0 + c] = h;
    g_al[row * CC0 + c] = __float2bfloat16(v - __bfloat162float(h));
}

// ======================= layer-0 mma GEMM: double-buffered smem + fragment pipelining =======================
template <int K, int N>
__global__ __launch_bounds__(256, 2) void k_mma(const __nv_bfloat16* __restrict__ Ah,
                                                const __nv_bfloat16* __restrict__ Al,
                                                const __nv_bfloat16* __restrict__ Bh,
                                                const __nv_bfloat16* __restrict__ Bl,
                                                const float* __restrict__ bias,
                                                float* __restrict__ Cout,
                                                float* __restrict__ sumArr,
                                                float* __restrict__ sqArr) {
    constexpr int KC  = 64;
    constexpr int CPS = K / KC;
    constexpr int NC  = 3 * CPS;
    constexpr uint32_t TB = 16384;

    extern __shared__ __align__(1024) char smem[];
    uint32_t sbase = smem_to_u32(smem);
    const uint32_t offA[2] = {0u, TB};
    const uint32_t offB[2] = {2u * TB, 3u * TB};

    int tid  = threadIdx.x;
    int wid  = tid >> 5, lane = tid & 31;
    int wm   = wid & 1;
    int wn   = wid >> 1;
    int blockRow = blockIdx.y * 128;
    int blockCol = blockIdx.x * 128;

    float acc[4][4][4];
#pragma unroll
    for (int i = 0; i < 4; i++)
#pragma unroll
        for (int j = 0; j < 4; j++)
#pragma unroll
            for (int l = 0; l < 4; l++) acc[i][j][l] = 0.f;

    int lr = tid >> 3;
    int lq = tid & 7;

    auto load_chunk = [&](int c, int buf) {
        int seg = c / CPS;
        int kb  = (c % CPS) * KC;
        const __nv_bfloat16* Asrc = (seg == 1) ? Al : Ah;
        const __nv_bfloat16* Bsrc = (seg == 2) ? Bl : Bh;
#pragma unroll
        for (int it = 0; it < 4; it++) {
            int r = it * 32 + lr;
            const void* gp = Asrc + (size_t)(blockRow + r) * K + kb + lq * 8;
            CP_ASYNC16(sbase + offA[buf] + SWZ128((uint32_t)(r * 128 + lq * 16)), gp);
        }
#pragma unroll
        for (int it = 0; it < 4; it++) {
            int n = it * 32 + lr;
            const void* gp = Bsrc + (size_t)(blockCol + n) * K + kb + lq * 8;
            CP_ASYNC16(sbase + offB[buf] + SWZ128((uint32_t)(n * 128 + lq * 16)), gp);
        }
    };

    int aRowL = (lane & 15);
    int aKoff = (lane >> 4) * 16;
    int bRowL = (lane & 7) + ((lane >> 4) << 3);
    int bKoff = ((lane >> 3) & 1) * 16;

    load_chunk(0, 0);
    CP_COMMIT();

    for (int c = 0; c < NC; c++) {
        int buf = c & 1;
        if (c + 1 < NC) {
            load_chunk(c + 1, buf ^ 1);
            CP_COMMIT();
            CP_WAIT(1);
        } else {
            CP_WAIT(0);
        }
        __syncthreads();

        uint32_t aBase = sbase + offA[buf];
        uint32_t bBase = sbase + offB[buf];

        // fragment-pipelined: prefetch kk+1's LDSM while kk's HMMAs drain
        uint32_t afr[2][4][4];
        uint32_t bfr[2][2][4];
#pragma unroll
        for (int mt = 0; mt < 4; mt++) {
            int row = wm * 64 + mt * 16 + aRowL;
            ldm_x4(afr[0][mt], aBase + SWZ128((uint32_t)(row * 128 + aKoff)));
        }
#pragma unroll
        for (int nt = 0; nt < 2; nt++) {
            int row = wn * 32 + nt * 16 + bRowL;
            ldm_x4(bfr[0][nt], bBase + SWZ128((uint32_t)(row * 128 + bKoff)));
        }
#pragma unroll
        for (int kk = 0; kk < 4; kk++) {
            int cur = kk & 1;
            if (kk < 3) {
                int nxt = cur ^ 1;
#pragma unroll
                for (int mt = 0; mt < 4; mt++) {
                    int row = wm * 64 + mt * 16 + aRowL;
                    ldm_x4(afr[nxt][mt], aBase + SWZ128((uint32_t)(row * 128 + (kk + 1) * 32 + aKoff)));
                }
#pragma unroll
                for (int nt = 0; nt < 2; nt++) {
                    int row = wn * 32 + nt * 16 + bRowL;
                    ldm_x4(bfr[nxt][nt], bBase + SWZ128((uint32_t)(row * 128 + (kk + 1) * 32 + bKoff)));
                }
            }
#pragma unroll
            for (int mt = 0; mt < 4; mt++)
#pragma unroll
                for (int n8 = 0; n8 < 4; n8++)
                    mma16816(acc[mt][n8], afr[cur][mt], &bfr[cur][n8 >> 1][(n8 & 1) * 2]);
        }
        __syncthreads();
    }

    int g = lane >> 2, tig = lane & 3;
    float sA[4][2], qA[4][2];
#pragma unroll
    for (int n8 = 0; n8 < 4; n8++) { sA[n8][0] = sA[n8][1] = qA[n8][0] = qA[n8][1] = 0.f; }

#pragma unroll
    for (int mt = 0; mt < 4; mt++) {
        int row0 = blockRow + wm * 64 + mt * 16 + g;
#pragma unroll
        for (int n8 = 0; n8 < 4; n8++) {
            int col = blockCol + wn * 32 + n8 * 8 + tig * 2;
            float b0 = __ldg(bias + col), b1 = __ldg(bias + col + 1);
            float2 v0 = make_float2(acc[mt][n8][0] + b0, acc[mt][n8][1] + b1);
            float2 v1 = make_float2(acc[mt][n8][2] + b0, acc[mt][n8][3] + b1);
            *reinterpret_cast<float2*>(Cout + (size_t)row0 * N + col) = v0;
            *reinterpret_cast<float2*>(Cout + (size_t)(row0 + 8) * N + col) = v1;
            sA[n8][0] += v0.x + v1.x;
            sA[n8][1] += v0.y + v1.y;
            qA[n8][0] = fmaf(v0.x, v0.x, fmaf(v1.x, v1.x, qA[n8][0]));
            qA[n8][1] = fmaf(v0.y, v0.y, fmaf(v1.y, v1.y, qA[n8][1]));
        }
    }
#pragma unroll
    for (int x = 4; x < 32; x <<= 1) {
#pragma unroll
        for (int n8 = 0; n8 < 4; n8++) {
            sA[n8][0] += __shfl_xor_sync(0xffffffffu, sA[n8][0], x);
            sA[n8][1] += __shfl_xor_sync(0xffffffffu, sA[n8][1], x);
            qA[n8][0] += __shfl_xor_sync(0xffffffffu, qA[n8][0], x);
            qA[n8][1] += __shfl_xor_sync(0xffffffffu, qA[n8][1], x);
        }
    }
    if (lane < 4) {
#pragma unroll
        for (int n8 = 0; n8 < 4; n8++) {
            int col = blockCol + wn * 32 + n8 * 8 + tig * 2;
            atomicAdd(sumArr + col,     sA[n8][0]);
            atomicAdd(sumArr + col + 1, sA[n8][1]);
            atomicAdd(sqArr + col,      qA[n8][0]);
            atomicAdd(sqArr + col + 1,  qA[n8][1]);
        }
    }
}

// ======================= layer-1 GEMM, fused BN0-finalize + BN0+relu+split A-producer =======================
__global__ __launch_bounds__(256) void k_mma1(const float* __restrict__ Y0,
                                              const __nv_bfloat16* __restrict__ Bh,
                                              const __nv_bfloat16* __restrict__ Bl,
                                              const float* __restrict__ sum0,
                                              const float* __restrict__ sq0,
                                              const float* __restrict__ scale0,
                                              const float* __restrict__ bnb0,
                                              const float* __restrict__ bias,
                                              float* __restrict__ Cout,
                                              float* __restrict__ sumArr,
                                              float* __restrict__ sqArr) {
    constexpr int K = 256, N = 128, CPS = 4;
    extern __shared__ __align__(1024) char smem[];
    uint32_t sbase = smem_to_u32(smem);
    const uint32_t offAh[2] = {0u, 32768u};
    const uint32_t offAl[2] = {16384u, 49152u};
    const uint32_t offBh = 65536u, offBl = 131072u;
    float* s_bnA = reinterpret_cast<float*>(smem + 196608);   // [256]
    float* s_bnC = s_bnA + 256;                                // [256]

    int tid = threadIdx.x, wid = tid >> 5, lane = tid & 31;
    int wm = wid & 1, wn = wid >> 1;
    int blockRow = blockIdx.y * 128;

    for (int gidx = tid; gidx < 4096; gidx += 256) {
        int n = gidx >> 5, kq = gidx & 31;
        int c = kq >> 3, qq = kq & 7;
        uint32_t so = SWZ128((uint32_t)(n * 128 + qq * 16)) + (uint32_t)c * 16384u;
        CP_ASYNC16(sbase + offBh + so, Bh + (size_t)n * K + kq * 8);
        CP_ASYNC16(sbase + offBl + so, Bl + (size_t)n * K + kq * 8);
    }
    CP_COMMIT();

    {
        float mu  = sum0[tid] * (1.f / (float)RTOT);
        float var = sq0[tid] * (1.f / (float)RTOT) - mu * mu;
        float a   = rsqrtf(var + 1e-5f) * scale0[tid];
        s_bnA[tid] = a;
        s_bnC[tid] = bnb0[tid] - mu * a;
    }

    float acc[4][4][4];
#pragma unroll
    for (int i = 0; i < 4; i++)
#pragma unroll
        for (int j = 0; j < 4; j++)
#pragma unroll
            for (int l = 0; l < 4; l++) acc[i][j][l] = 0.f;

    float4 stg[8];
    auto ldgA = [&](int c) {
#pragma unroll
        for (int it = 0; it < 8; it++) {
            int gi = it * 256 + tid;
            int r = gi >> 4, kq4 = gi & 15;
            stg[it] = *reinterpret_cast<const float4*>(
                Y0 + (size_t)(blockRow + r) * K + c * 64 + kq4 * 4);
        }
    };
    auto stsA = [&](int c, int buf) {
#pragma unroll
        for (int it = 0; it < 8; it++) {
            int gi = it * 256 + tid;
            int r = gi >> 4, kq4 = gi & 15;
            int k = c * 64 + kq4 * 4;
            float4 a4 = *reinterpret_cast<const float4*>(s_bnA + k);
            float4 c4 = *reinterpret_cast<const float4*>(s_bnC + k);
            float v0 = fmaxf(fmaf(stg[it].x, a4.x, c4.x), 0.f);
            float v1 = fmaxf(fmaf(stg[it].y, a4.y, c4.y), 0.f);
            float v2 = fmaxf(fmaf(stg[it].z, a4.z, c4.z), 0.f);
            float v3 = fmaxf(fmaf(stg[it].w, a4.w, c4.w), 0.f);
            __nv_bfloat16 h0 = __float2bfloat16(v0), h1 = __float2bfloat16(v1);
            __nv_bfloat16 h2 = __float2bfloat16(v2), h3 = __float2bfloat16(v3);
            __nv_bfloat162 hp0; hp0.x = h0; hp0.y = h1;
            __nv_bfloat162 hp1; hp1.x = h2; hp1.y = h3;
            __nv_bfloat162 lp0, lp1;
            lp0.x = __float2bfloat16(v0 - __bfloat162float(h0));
            lp0.y = __float2bfloat16(v1 - __bfloat162float(h1));
            lp1.x = __float2bfloat16(v2 - __bfloat162float(h2));
            lp1.y = __float2bfloat16(v3 - __bfloat162float(h3));
            uint32_t sw = SWZ128((uint32_t)(r * 128 + (kq4 >> 1) * 16)) + (uint32_t)(kq4 & 1) * 8u;
            uint2 hv = make_uint2(*reinterpret_cast<uint32_t*>(&hp0),
                                  *reinterpret_cast<uint32_t*>(&hp1));
            uint2 lv = make_uint2(*reinterpret_cast<uint32_t*>(&lp0),
                                  *reinterpret_cast<uint32_t*>(&lp1));
            *reinterpret_cast<uint2*>(smem + offAh[buf] + sw) = hv;
            *reinterpret_cast<uint2*>(smem + offAl[buf] + sw) = lv;
        }
    };

    int aRowL = (lane & 15);
    int aKoff = (lane >> 4) * 16;
    int bRowL = (lane & 7) + ((lane >> 4) << 3);
    int bKoff = ((lane >> 3) & 1) * 16;

    ldgA(0);
    __syncthreads();
    stsA(0, 0);
    CP_WAIT(0);
    __syncthreads();

    for (int c = 0; c < CPS; c++) {
        int buf = c & 1;
        if (c + 1 < CPS) ldgA(c + 1);

        uint32_t bCh = sbase + offBh + (uint32_t)c * 16384u;
        uint32_t bCl = sbase + offBl + (uint32_t)c * 16384u;
#pragma unroll
        for (int pass = 0; pass < 3; pass++) {
            uint32_t aBase = sbase + ((pass == 1) ? offAl[buf] : offAh[buf]);
            uint32_t bBase = (pass == 2) ? bCl : bCh;
#pragma unroll
            for (int kk = 0; kk < 4; kk++) {
                uint32_t afr[4][4];
#pragma unroll
                for (int mt = 0; mt < 4; mt++) {
                    int row = wm * 64 + mt * 16 + aRowL;
                    ldm_x4(afr[mt], aBase + SWZ128((uint32_t)(row * 128 + kk * 32 + aKoff)));
                }
                uint32_t bfr[2][4];
#pragma unroll
                for (int nt = 0; nt < 2; nt++) {
                    int row = wn * 32 + nt * 16 + bRowL;
                    ldm_x4(bfr[nt], bBase + SWZ128((uint32_t)(row * 128 + kk * 32 + bKoff)));
                }
#pragma unroll
                for (int mt = 0; mt < 4; mt++)
#pragma unroll
                    for (int n8 = 0; n8 < 4; n8++)
                        mma16816(acc[mt][n8], afr[mt], &bfr[n8 >> 1][(n8 & 1) * 2]);
            }
        }
        if (c + 1 < CPS) stsA(c + 1, buf ^ 1);
        __syncthreads();
    }

    int g = lane >> 2, tig = lane & 3;
    float sA[4][2], qA[4][2];
#pragma unroll
    for (int n8 = 0; n8 < 4; n8++) { sA[n8][0] = sA[n8][1] = qA[n8][0] = qA[n8][1] = 0.f; }

#pragma unroll
    for (int mt = 0; mt < 4; mt++) {
        int row0 = blockRow + wm * 64 + mt * 16 + g;
#pragma unroll
        for (int n8 = 0; n8 < 4; n8++) {
            int col = wn * 32 + n8 * 8 + tig * 2;
            float b0 = __ldg(bias + col), b1 = __ldg(bias + col + 1);
            float2 v0 = make_float2(acc[mt][n8][0] + b0, acc[mt][n8][1] + b1);
            float2 v1 = make_float2(acc[mt][n8][2] + b0, acc[mt][n8][3] + b1);
            *reinterpret_cast<float2*>(Cout + (size_t)row0 * N + col) = v0;
            *reinterpret_cast<float2*>(Cout + (size_t)(row0 + 8) * N + col) = v1;
            sA[n8][0] += v0.x + v1.x;
            sA[n8][1] += v0.y + v1.y;
            qA[n8][0] = fmaf(v0.x, v0.x, fmaf(v1.x, v1.x, qA[n8][0]));
            qA[n8][1] = fmaf(v0.y, v0.y, fmaf(v1.y, v1.y, qA[n8][1]));
        }
    }
#pragma unroll
    for (int x = 4; x < 32; x <<= 1) {
#pragma unroll
        for (int n8 = 0; n8 < 4; n8++) {
            sA[n8][0] += __shfl_xor_sync(0xffffffffu, sA[n8][0], x);
            sA[n8][1] += __shfl_xor_sync(0xffffffffu, sA[n8][1], x);
            qA[n8][0] += __shfl_xor_sync(0xffffffffu, qA[n8][0], x);
            qA[n8][1] += __shfl_xor_sync(0xffffffffu, qA[n8][1], x);
        }
    }
    if (lane < 4) {
#pragma unroll
        for (int n8 = 0; n8 < 4; n8++) {
            int col = wn * 32 + n8 * 8 + tig * 2;
            atomicAdd(sumArr + col,     sA[n8][0]);
            atomicAdd(sumArr + col + 1, sA[n8][1]);
            atomicAdd(sqArr + col,      qA[n8][0]);
            atomicAdd(sqArr + col + 1,  qA[n8][1]);
        }
    }
}

// BN1-finalize (per block) + BN1 + relu + transpose to [B, C2, N]
__global__ __launch_bounds__(256) void k_out(const float* __restrict__ sum1,
                                             const float* __restrict__ sq1,
                                             const float* __restrict__ scale1,
                                             const float* __restrict__ bnb1,
                                             float* __restrict__ out) {
    __shared__ float tile[32][33];
    __shared__ float s_a1[32], s_c1[32];
    int b = blockIdx.z, n0 = blockIdx.x * 32, c0 = blockIdx.y * 32;
    int tx = threadIdx.x, ty = threadIdx.y;
    int flat = ty * 32 + tx;
    if (flat < 32) {
        int c = c0 + flat;
        float mu  = sum1[c] * (1.f / (float)RTOT);
        float var = sq1[c] * (1.f / (float)RTOT) - mu * mu;
        float a   = rsqrtf(var + 1e-5f) * scale1[c];
        s_a1[flat] = a;
        s_c1[flat] = bnb1[c] - mu * a;
    }
    __syncthreads();
#pragma unroll
    for (int j = 0; j < 4; j++) {
        int n = n0 + ty + j * 8;
        float v = g_y1[((size_t)b * NP + n) * CC2 + c0 + tx];
        v = fmaxf(fmaf(v, s_a1[tx], s_c1[tx]), 0.f);
        tile[ty + j * 8][tx] = v;
    }
    __syncthreads();
#pragma unroll
    for (int j = 0; j < 4; j++) {
        int c = c0 + ty + j * 8;
        out[((size_t)b * CC2 + c) * NP + n0 + tx] = tile[tx][ty + j * 8];
    }
}

// ======================= launch =======================
extern "C" void kernel_launch(void* const* d_in, const int* in_sizes, int n_in,
                              void* d_out, int out_size) {
    const float* xyz1 = (const float*)d_in[0];
    const float* xyz2 = (const float*)d_in[1];
    const float* pts1 = (const float*)d_in[2];
    const float* pts2 = (const float*)d_in[3];
    const float* cw0  = (const float*)d_in[4];
    const float* cb0  = (const float*)d_in[5];
    const float* bns0 = (const float*)d_in[6];
    const float* bnb0 = (const float*)d_in[7];
    const float* cw1  = (const float*)d_in[8];
    const float* cb1  = (const float*)d_in[9];
    const float* bns1 = (const float*)d_in[10];
    const float* bnb1 = (const float*)d_in[11];
    float* out = (float*)d_out;

    float *p_y0, *p_y1, *p_sum0, *p_sq0, *p_sum1, *p_sq1;
    __nv_bfloat16 *p_ah, *p_al, *p_wh0, *p_wl0, *p_wh1, *p_wl1;
    cudaGetSymbolAddress((void**)&p_y0, g_y0);
    cudaGetSymbolAddress((void**)&p_y1, g_y1);
    cudaGetSymbolAddress((void**)&p_sum0, g_sum0);
    cudaGetSymbolAddress((void**)&p_sq0, g_sq0);
    cudaGetSymbolAddress((void**)&p_sum1, g_sum1);
    cudaGetSymbolAddress((void**)&p_sq1, g_sq1);
    cudaGetSymbolAddress((void**)&p_ah, g_ah);
    cudaGetSymbolAddress((void**)&p_al, g_al);
    cudaGetSymbolAddress((void**)&p_wh0, g_wh0);
    cudaGetSymbolAddress((void**)&p_wl0, g_wl0);
    cudaGetSymbolAddress((void**)&p_wh1, g_wh1);
    cudaGetSymbolAddress((void**)&p_wl1, g_wl1);

    constexpr int SMEM_MMA  = 4 * 16384;          // 64KB  (layer 0, 2 stages)
    constexpr int SMEM_MMA1 = 192 * 1024 + 2048;  // 194KB (layer 1 + bn coeffs)
    cudaFuncSetAttribute((void*)k_mma<CC0, CC1>, cudaFuncAttributeMaxDynamicSharedMemorySize, SMEM_MMA);
    cudaFuncSetAttribute((void*)k_mma1, cudaFuncAttributeMaxDynamicSharedMemorySize, SMEM_MMA1);

    k_prep<<<6465, 256>>>(pts2, pts1, cw0, cw1);
    k_knn<<<dim3(NP / 256, BB), 512>>>(xyz1, xyz2);
    k_gather<<<RTOT, 192>>>();

    // layer 0: [R,192] x [256,192]^T -> y0 [R,256]  (+ fused stats)
    k_mma<CC0, CC1><<<dim3(CC1 / 128, RTOT / 128), 256, SMEM_MMA>>>(
        p_ah, p_al, p_wh0, p_wl0, cb0, p_y0, p_sum0, p_sq0);

    // layer 1: fused BN0-finalize + BN0+relu+split producer (+ fused stats)
    k_mma1<<<dim3(1, RTOT / 128), 256, SMEM_MMA1>>>(
        p_y0, p_wh1, p_wl1, p_sum0, p_sq0, bns0, bnb0, cb1, p_y1, p_sum1, p_sq1);

    // output: fused BN1-finalize + BN1 + relu + transpose
    k_out<<<dim3(NP / 32, CC2 / 32, BB), dim3(32, 8)>>>(p_sum1, p_sq1, bns1, bnb1, out);
}